// round 14
// baseline (speedup 1.0000x reference)
#include <cuda_runtime.h>
#include <math.h>

// ---------------------------------------------------------------------------
// GraphSAGE, 2 layers:
//   h1 = relu([F | wmean_gather(F)] @ W1^T)        for all N nodes
//   h2 = relu([h1 | wmean_gather(h1)] @ W2^T)      for the 8192 batch nodes
//   out = h2
// ---------------------------------------------------------------------------

#define N_NODES   100000
#define DIM       256
#define OUT_DIM   256
#define TWO_D     512
#define KNEIGH    10
#define BATCH_B   8192

#define BM        64
#define BK        16
#define NTHREADS  256
#define AS_STRIDE 516   // 512 + 4 pad -> bank-conflict-free column reads
#define BS_STRIDE 260   // 256 + 4 pad -> conflict-free transposed stores, f4-aligned rows

// smem layout (floats):
//   As   [BM * AS_STRIDE]      = 33024
//   Bs   [BK * BS_STRIDE]      =  4160
//   s_w  [BM * KNEIGH]         =   640
//   s_wsum [BM]                =    64
//   s_nid (int) [BM * KNEIGH]  =   640
//   s_node (int) [BM]          =    64
static const int SMEM_FLOATS = BM * AS_STRIDE + BK * BS_STRIDE + BM * KNEIGH + BM
                             + BM * KNEIGH + BM;
static const int SMEM_BYTES  = SMEM_FLOATS * 4;   // 154368

// scratch for layer-1 activations (allowed: __device__ global, no runtime alloc)
__device__ float g_h1[(size_t)N_NODES * OUT_DIM];

template <bool USE_BATCH>
__global__ __launch_bounds__(NTHREADS, 1)
void sage_layer_kernel(const float* __restrict__ Hext,   // features (layer 1 only)
                       const int*   __restrict__ neigh,  // [N, K]
                       const float* __restrict__ ec,     // [N, K]
                       const float* __restrict__ Wp,     // [256, 512] row-major
                       const int*   __restrict__ batch,  // [B] (layer 2 only)
                       float*       __restrict__ outext, // d_out (layer 2 only)
                       int n_rows)
{
    extern __shared__ float smem[];
    float* As     = smem;
    float* Bs     = As + BM * AS_STRIDE;
    float* s_w    = Bs + BK * BS_STRIDE;
    float* s_wsum = s_w + BM * KNEIGH;
    int*   s_nid  = (int*)(s_wsum + BM);
    int*   s_node = s_nid + BM * KNEIGH;

    const int tid  = threadIdx.x;
    const int row0 = blockIdx.x * BM;

    const float* Hin = USE_BATCH ? (const float*)g_h1 : Hext;
    float*       Dst = USE_BATCH ? outext : (float*)g_h1;

    // ---- phase 0: node ids + weight sums ------------------------------------
    if (tid < BM) {
        int   r  = row0 + tid;
        int   v  = -1;
        float ws = 1.0f;
        if (r < n_rows) {
            v = USE_BATCH ? batch[r] : r;
            float s = 0.0f;
            #pragma unroll
            for (int k = 0; k < KNEIGH; k++)
                s += ec[(size_t)v * KNEIGH + k];
            ws = fmaxf(s, 1e-12f);
        }
        s_node[tid] = v;
        s_wsum[tid] = ws;
    }
    __syncthreads();

    // ---- phase 0b: neighbor ids + normalized weights into smem --------------
    for (int p = tid; p < BM * KNEIGH; p += NTHREADS) {
        int m = p / KNEIGH;
        int k = p - m * KNEIGH;
        int v = s_node[m];
        int   u = 0;
        float w = 0.0f;
        if (v >= 0) {
            u = neigh[(size_t)v * KNEIGH + k];
            w = ec[(size_t)v * KNEIGH + k] / s_wsum[m];
        }
        s_nid[p] = u;
        s_w[p]   = w;
    }

    // prefetch first W tile into registers (independent of smem state)
    float4 breg[4];
    #pragma unroll
    for (int j = 0; j < 4; j++) {
        int f = tid + NTHREADS * j;
        int n = f >> 2, kq = f & 3;
        breg[j] = *(const float4*)(Wp + (size_t)n * TWO_D + kq * 4);
    }
    __syncthreads();

    // ---- phase 1: build combined tile As[m][0:256]=own, [256:512]=agg -------
    {
        const int cq = tid & 63;   // column quad: cols cq*4 .. cq*4+3
        const int mg = tid >> 6;   // 0..3 -> rows mg*16 .. mg*16+15
        for (int mm = 0; mm < BM / 4; mm++) {
            int m = mg * (BM / 4) + mm;
            int v = s_node[m];
            float4 own = make_float4(0.f, 0.f, 0.f, 0.f);
            float4 agg = make_float4(0.f, 0.f, 0.f, 0.f);
            if (v >= 0) {
                own = *(const float4*)(Hin + (size_t)v * DIM + cq * 4);
                #pragma unroll
                for (int k = 0; k < KNEIGH; k++) {
                    float  w  = s_w[m * KNEIGH + k];
                    float4 hv = *(const float4*)(Hin + (size_t)s_nid[m * KNEIGH + k] * DIM + cq * 4);
                    agg.x = fmaf(w, hv.x, agg.x);
                    agg.y = fmaf(w, hv.y, agg.y);
                    agg.z = fmaf(w, hv.z, agg.z);
                    agg.w = fmaf(w, hv.w, agg.w);
                }
            }
            *(float4*)(As + m * AS_STRIDE + cq * 4)       = own;
            *(float4*)(As + m * AS_STRIDE + DIM + cq * 4) = agg;
        }
    }
    __syncthreads();

    // ---- phase 2: GEMM  C[m][n] = sum_k As[m][k] * W[n][k], relu, store -----
    const int tn = tid & 15;    // n = tn*16 .. tn*16+15
    const int tm = tid >> 4;    // m = tm*4  .. tm*4+3

    float acc[4][16];
    #pragma unroll
    for (int i = 0; i < 4; i++)
        #pragma unroll
        for (int j = 0; j < 16; j++)
            acc[i][j] = 0.0f;

    const int nTiles = TWO_D / BK;   // 32
    for (int t = 0; t < nTiles; t++) {
        // commit prefetched tile to smem (transposed: Bs[kk][n] = W[n][t*BK+kk])
        #pragma unroll
        for (int j = 0; j < 4; j++) {
            int f = tid + NTHREADS * j;
            int n = f >> 2, kq = f & 3;
            Bs[(kq * 4 + 0) * BS_STRIDE + n] = breg[j].x;
            Bs[(kq * 4 + 1) * BS_STRIDE + n] = breg[j].y;
            Bs[(kq * 4 + 2) * BS_STRIDE + n] = breg[j].z;
            Bs[(kq * 4 + 3) * BS_STRIDE + n] = breg[j].w;
        }
        __syncthreads();

        // prefetch next tile (hides L2 latency behind the FMA burst)
        if (t + 1 < nTiles) {
            int k0 = (t + 1) * BK;
            #pragma unroll
            for (int j = 0; j < 4; j++) {
                int f = tid + NTHREADS * j;
                int n = f >> 2, kq = f & 3;
                breg[j] = *(const float4*)(Wp + (size_t)n * TWO_D + k0 + kq * 4);
            }
        }

        const float* Abase = As + t * BK;
        #pragma unroll
        for (int kk = 0; kk < BK; kk++) {
            float a0 = Abase[(tm * 4 + 0) * AS_STRIDE + kk];
            float a1 = Abase[(tm * 4 + 1) * AS_STRIDE + kk];
            float a2 = Abase[(tm * 4 + 2) * AS_STRIDE + kk];
            float a3 = Abase[(tm * 4 + 3) * AS_STRIDE + kk];
            const float* brow = Bs + kk * BS_STRIDE + tn * 16;
            float4 b0 = *(const float4*)(brow + 0);
            float4 b1 = *(const float4*)(brow + 4);
            float4 b2 = *(const float4*)(brow + 8);
            float4 b3 = *(const float4*)(brow + 12);
            float bb[16] = { b0.x, b0.y, b0.z, b0.w,  b1.x, b1.y, b1.z, b1.w,
                             b2.x, b2.y, b2.z, b2.w,  b3.x, b3.y, b3.z, b3.w };
            #pragma unroll
            for (int j = 0; j < 16; j++) {
                acc[0][j] = fmaf(a0, bb[j], acc[0][j]);
                acc[1][j] = fmaf(a1, bb[j], acc[1][j]);
                acc[2][j] = fmaf(a2, bb[j], acc[2][j]);
                acc[3][j] = fmaf(a3, bb[j], acc[3][j]);
            }
        }
        __syncthreads();
    }

    // ---- epilogue: relu + store ---------------------------------------------
    #pragma unroll
    for (int i = 0; i < 4; i++) {
        int r = row0 + tm * 4 + i;
        if (r < n_rows) {
            float* dst = Dst + (size_t)r * OUT_DIM + tn * 16;
            #pragma unroll
            for (int j = 0; j < 16; j += 4) {
                float4 o = make_float4(fmaxf(acc[i][j + 0], 0.f),
                                       fmaxf(acc[i][j + 1], 0.f),
                                       fmaxf(acc[i][j + 2], 0.f),
                                       fmaxf(acc[i][j + 3], 0.f));
                *(float4*)(dst + j) = o;
            }
        }
    }
}

extern "C" void kernel_launch(void* const* d_in, const int* in_sizes, int n_in,
                              void* d_out, int out_size)
{
    const float* features = (const float*)d_in[0];  // [N, 256]
    const int*   neigh    = (const int*)  d_in[1];  // [N, 10]
    const float* ec       = (const float*)d_in[2];  // [N, 10]
    const float* W1       = (const float*)d_in[3];  // [256, 512]
    const float* W2       = (const float*)d_in[4];  // [256, 512]
    const int*   batch    = (const int*)  d_in[5];  // [8192]
    float*       out      = (float*)      d_out;    // [8192, 256]

    // opt-in dynamic smem (idempotent; safe under graph capture)
    cudaFuncSetAttribute((const void*)sage_layer_kernel<false>,
                         cudaFuncAttributeMaxDynamicSharedMemorySize, SMEM_BYTES);
    cudaFuncSetAttribute((const void*)sage_layer_kernel<true>,
                         cudaFuncAttributeMaxDynamicSharedMemorySize, SMEM_BYTES);

    // layer 1: all N nodes -> g_h1
    int blocks1 = (N_NODES + BM - 1) / BM;   // 1563
    sage_layer_kernel<false><<<blocks1, NTHREADS, SMEM_BYTES>>>(
        features, neigh, ec, W1, nullptr, nullptr, N_NODES);

    // layer 2: batch nodes, reads g_h1 -> d_out
    int blocks2 = (BATCH_B + BM - 1) / BM;   // 128
    sage_layer_kernel<true><<<blocks2, NTHREADS, SMEM_BYTES>>>(
        nullptr, neigh, ec, W2, batch, out, BATCH_B);
}